// round 4
// baseline (speedup 1.0000x reference)
#include <cuda_runtime.h>
#include <math.h>

#define HDIM 384
#define WDIM 384
#define HW (HDIM*WDIM)            // 147456
#define SUMN 128
#define BATCH 16
#define LAG 8
#define NEGV -1000000000.0f
#define BLOCKS_PER_IMG 144        // 147456 / (256*4)

// Scratch (no cudaMalloc allowed)
__device__ float g_conf[(size_t)SUMN * HW];   // 75.5 MB
__device__ float g_meanconf[SUMN];
__device__ float g_overlap[SUMN];
__device__ float g_demand[BATCH];

__device__ __forceinline__ float blockReduceSum256(float v) {
    for (int o = 16; o > 0; o >>= 1) v += __shfl_down_sync(0xffffffffu, v, o);
    __shared__ float ws[8];
    int lane = threadIdx.x & 31, wid = threadIdx.x >> 5;
    if (lane == 0) ws[wid] = v;
    __syncthreads();
    if (wid == 0) {
        v = (lane < 8) ? ws[lane] : 0.0f;
        for (int o = 4; o > 0; o >>= 1) v += __shfl_down_sync(0xffffffffu, v, o);
    }
    return v;  // valid in thread 0
}

__global__ void k_zero() {
    int t = threadIdx.x;
    if (t < SUMN) { g_meanconf[t] = 0.0f; g_overlap[t] = 0.0f; }
    if (t < BATCH) g_demand[t] = 0.0f;
}

// Kernel 1: conf = sigmoid(max(ch0, ch1)), accumulate mean_conf[n] and demand[b]
__global__ void __launch_bounds__(256) k_conf(const float* __restrict__ psm,
                                              const float* __restrict__ req) {
    int n    = blockIdx.x / BLOCKS_PER_IMG;
    int tile = blockIdx.x % BLOCKS_PER_IMG;
    int p0   = tile * 1024 + threadIdx.x * 4;

    const float4 a4 = *(const float4*)(psm + (size_t)n * 2 * HW + p0);
    const float4 b4 = *(const float4*)(psm + (size_t)n * 2 * HW + HW + p0);
    float a[4] = {a4.x, a4.y, a4.z, a4.w};
    float b[4] = {b4.x, b4.y, b4.z, b4.w};

    float4 c4;
    float cs[4];
    float sum = 0.0f;
    #pragma unroll
    for (int u = 0; u < 4; u++) {
        float m = fmaxf(a[u], b[u]);
        float s = __fdividef(1.0f, 1.0f + __expf(-m));
        cs[u] = s;
        sum += s;
    }
    c4.x = cs[0]; c4.y = cs[1]; c4.z = cs[2]; c4.w = cs[3];
    *(float4*)(g_conf + (size_t)n * HW + p0) = c4;

    float dsum = 0.0f;
    bool ego = ((n & (LAG - 1)) == 0);
    if (ego) {
        const float4 r4 = *(const float4*)(req + (size_t)n * HW + p0);
        dsum = r4.x + r4.y + r4.z + r4.w;
    }

    float bs = blockReduceSum256(sum);
    if (threadIdx.x == 0) atomicAdd(&g_meanconf[n], bs);
    __syncthreads();
    if (ego) {
        float bd = blockReduceSum256(dsum);
        if (threadIdx.x == 0) atomicAdd(&g_demand[n >> 3], bd);
    }
}

// Kernel 2: warped = bilinear(conf[b,l], A=norm_affine[b,0,l]); overlap sum of Di * warped
__global__ void __launch_bounds__(256) k_warp(const float* __restrict__ req,
                                              const float* __restrict__ na) {
    int n    = blockIdx.x / BLOCKS_PER_IMG;
    int tile = blockIdx.x % BLOCKS_PER_IMG;
    int b = n >> 3, l = n & (LAG - 1);

    const float* A = na + (size_t)((b * LAG + 0) * LAG + l) * 6;
    float A00 = __ldg(A + 0), A01 = __ldg(A + 1), A02 = __ldg(A + 2);
    float A10 = __ldg(A + 3), A11 = __ldg(A + 4), A12 = __ldg(A + 5);

    const float* cimg = g_conf + (size_t)n * HW;
    int p0 = tile * 1024 + threadIdx.x * 4;
    const float4 d4 = *(const float4*)(req + (size_t)(b * LAG) * HW + p0);
    float di[4] = {d4.x, d4.y, d4.z, d4.w};

    const float step = 2.0f / 383.0f;
    float sum = 0.0f;
    #pragma unroll
    for (int u = 0; u < 4; u++) {
        int p = p0 + u;
        int i = p / WDIM;
        int j = p - i * WDIM;
        float gx = fmaf((float)j, step, -1.0f);
        float gy = fmaf((float)i, step, -1.0f);
        float sx = fmaf(A00, gx, fmaf(A01, gy, A02));
        float sy = fmaf(A10, gx, fmaf(A11, gy, A12));
        float px = (sx + 1.0f) * (0.5f * (WDIM - 1));
        float py = (sy + 1.0f) * (0.5f * (HDIM - 1));
        float x0f = floorf(px), y0f = floorf(py);
        float wx = px - x0f, wy = py - y0f;
        int x0 = (int)x0f, y0 = (int)y0f;

        float v00 = 0.0f, v01 = 0.0f, v10 = 0.0f, v11 = 0.0f;
        bool xv0 = (unsigned)x0 < (unsigned)WDIM;
        bool xv1 = (unsigned)(x0 + 1) < (unsigned)WDIM;
        bool yv0 = (unsigned)y0 < (unsigned)HDIM;
        bool yv1 = (unsigned)(y0 + 1) < (unsigned)HDIM;
        if (yv0) {
            const float* row = cimg + (size_t)y0 * WDIM;
            if (xv0) v00 = __ldg(row + x0);
            if (xv1) v01 = __ldg(row + x0 + 1);
        }
        if (yv1) {
            const float* row = cimg + (size_t)(y0 + 1) * WDIM;
            if (xv0) v10 = __ldg(row + x0);
            if (xv1) v11 = __ldg(row + x0 + 1);
        }
        float top = v00 * (1.0f - wx) + v01 * wx;
        float bot = v10 * (1.0f - wx) + v11 * wx;
        float val = top * (1.0f - wy) + bot * wy;
        sum += di[u] * val;
    }

    float bs = blockReduceSum256(sum);
    if (threadIdx.x == 0) atomicAdd(&g_overlap[n], bs);
}

// Kernel 3: all the tiny MLP work. One block of 1024 threads.
__global__ void __launch_bounds__(1024, 1)
k_head(const float* __restrict__ na,
       const float* __restrict__ qW1, const float* __restrict__ qb1,
       const float* __restrict__ qW2, const float* __restrict__ qb2,
       const float* __restrict__ kW1, const float* __restrict__ kb1,
       const float* __restrict__ kW2, const float* __restrict__ kb2,
       const float* __restrict__ eW1, const float* __restrict__ eb1,
       const float* __restrict__ eW2, const float* __restrict__ eb2,
       float* __restrict__ out) {
    extern __shared__ float sm[];
    float* s_feat = sm;            // 128*8   = 1024
    float* s_ego  = sm + 1024;     // 16*8    = 128
    float* s_q    = sm + 1152;     // 16*64   = 1024
    float* s_h    = sm + 2176;     // 16*64   = 1024
    float* s_bufA = sm + 3200;     // 128*64  = 8192
    float* s_bufB = sm + 11392;    // 128*64  = 8192

    int t = threadIdx.x;
    const float invHW = 1.0f / (float)HW;

    // Phase 1: scalar features
    if (t < SUMN) {
        int b = t >> 3, l = t & 7;
        float mc = g_meanconf[t] * invHW;
        float ov = g_overlap[t] * invHW;
        float dm = g_demand[b] * invHW;
        const float* A = na + (size_t)((b * LAG + 0) * LAG + l) * 6;
        float dx = A[2], dy = A[5];
        float dist = sqrtf(dx * dx + dy * dy);
        const float* D  = na + (size_t)((b * LAG + l) * LAG + l) * 6;
        const float* D0 = na + (size_t)((b * LAG + 0) * LAG + 0) * 6;
        float yaw  = atan2f(D[3], D[0]);
        float yaw0 = atan2f(D0[3], D0[0]);
        float d = yaw0 - yaw;
        float cosd = cosf(d), sind = sinf(d);
        s_feat[t * 8 + 0] = mc;
        s_feat[t * 8 + 1] = ov;
        s_feat[t * 8 + 2] = dx;
        s_feat[t * 8 + 3] = dy;
        s_feat[t * 8 + 4] = cosd;
        s_feat[t * 8 + 5] = sind;
        s_feat[t * 8 + 6] = dist;
        s_feat[t * 8 + 7] = dm;
    }
    if (t < BATCH) {
        float dm = g_demand[t] * invHW;
        float mc0 = g_meanconf[t * LAG] * invHW;
        s_ego[t * 8 + 0] = mc0;
        s_ego[t * 8 + 1] = dm;
        s_ego[t * 8 + 2] = 0.0f;
        s_ego[t * 8 + 3] = 0.0f;
        s_ego[t * 8 + 4] = 1.0f;
        s_ego[t * 8 + 5] = 0.0f;
        s_ego[t * 8 + 6] = 0.0f;
        s_ego[t * 8 + 7] = dm;
    }
    __syncthreads();

    // Phase 2: q-MLP (16 rows). t in [0,1024): b = t/64, j = t%64
    {
        int b = t >> 6, j = t & 63;
        float acc = qb1[j];
        #pragma unroll
        for (int i = 0; i < 8; i++) acc = fmaf(s_ego[b * 8 + i], qW1[i * 64 + j], acc);
        s_h[t] = fmaxf(acc, 0.0f);
    }
    __syncthreads();
    {
        int b = t >> 6, j = t & 63;
        float acc = qb2[j];
        #pragma unroll
        for (int i = 0; i < 64; i++) acc = fmaf(s_h[b * 64 + i], qW2[i * 64 + j], acc);
        s_q[t] = acc;
    }
    __syncthreads();

    // Phase 3: k-MLP (128 rows). 8 outputs per thread.
    #pragma unroll
    for (int c = 0; c < 8; c++) {
        int o = t + c * 1024;
        int r = o >> 6, j = o & 63;
        float acc = kb1[j];
        #pragma unroll
        for (int i = 0; i < 8; i++) acc = fmaf(s_feat[r * 8 + i], kW1[i * 64 + j], acc);
        s_bufA[o] = fmaxf(acc, 0.0f);
    }
    __syncthreads();
    #pragma unroll
    for (int c = 0; c < 8; c++) {
        int o = t + c * 1024;
        int r = o >> 6, j = o & 63;
        float acc = kb2[j];
        #pragma unroll
        for (int i = 0; i < 64; i++) acc = fmaf(s_bufA[r * 64 + i], kW2[i * 64 + j], acc);
        s_bufB[o] = acc;
    }
    __syncthreads();

    // Phase 4: e-MLP hidden: input = [q[b], k[r]]
    #pragma unroll
    for (int c = 0; c < 8; c++) {
        int o = t + c * 1024;
        int r = o >> 6, j = o & 63;
        int b = r >> 3;
        float acc = eb1[j];
        #pragma unroll
        for (int i = 0; i < 64; i++) acc = fmaf(s_q[b * 64 + i], eW1[i * 64 + j], acc);
        #pragma unroll
        for (int i = 0; i < 64; i++) acc = fmaf(s_bufB[r * 64 + i], eW1[(64 + i) * 64 + j], acc);
        s_bufA[o] = fmaxf(acc, 0.0f);
    }
    __syncthreads();

    // Phase 5: logits + sigmoid + clip
    if (t < SUMN) {
        float acc = eb2[0];
        #pragma unroll
        for (int j = 0; j < 64; j++) acc = fmaf(s_bufA[t * 64 + j], eW2[j], acc);
        if ((t & 7) == 0) acc = NEGV;
        float s = 1.0f / (1.0f + expf(-acc));
        out[t] = fminf(fmaxf(s, 0.0f), 1.0f);
    }
}

extern "C" void kernel_launch(void* const* d_in, const int* in_sizes, int n_in,
                              void* d_out, int out_size) {
    const float* psm  = (const float*)d_in[0];
    const float* req  = (const float*)d_in[1];
    const float* na   = (const float*)d_in[2];
    // d_in[3] = record_len (unused, always L)
    const float* qW1 = (const float*)d_in[4];
    const float* qb1 = (const float*)d_in[5];
    const float* qW2 = (const float*)d_in[6];
    const float* qb2 = (const float*)d_in[7];
    const float* kW1 = (const float*)d_in[8];
    const float* kb1 = (const float*)d_in[9];
    const float* kW2 = (const float*)d_in[10];
    const float* kb2 = (const float*)d_in[11];
    const float* eW1 = (const float*)d_in[12];
    const float* eb1 = (const float*)d_in[13];
    const float* eW2 = (const float*)d_in[14];
    const float* eb2 = (const float*)d_in[15];
    float* out = (float*)d_out;

    cudaFuncSetAttribute(k_head, cudaFuncAttributeMaxDynamicSharedMemorySize, 19584 * 4);

    k_zero<<<1, 256>>>();
    k_conf<<<SUMN * BLOCKS_PER_IMG, 256>>>(psm, req);
    k_warp<<<SUMN * BLOCKS_PER_IMG, 256>>>(req, na);
    k_head<<<1, 1024, 19584 * 4>>>(na, qW1, qb1, qW2, qb2, kW1, kb1, kW2, kb2,
                                   eW1, eb1, eW2, eb2, out);
}

// round 5
// speedup vs baseline: 1.5174x; 1.5174x over previous
#include <cuda_runtime.h>
#include <cuda_fp16.h>
#include <math.h>

#define HDIM 384
#define WDIM 384
#define HW (HDIM*WDIM)            // 147456
#define SUMN 128
#define BATCH 16
#define LAG 8
#define NEGV -1000000000.0f
#define BLOCKS_PER_IMG 72         // 147456 / (256*8)

// Scratch (no cudaMalloc allowed)
__device__ __half g_conf[(size_t)SUMN * HW];   // 37.7 MB
__device__ float g_meanconf[SUMN];
__device__ float g_overlap[SUMN];
__device__ float g_demand[BATCH];

__device__ __forceinline__ float blockReduceSum256(float v) {
    for (int o = 16; o > 0; o >>= 1) v += __shfl_down_sync(0xffffffffu, v, o);
    __shared__ float ws[8];
    int lane = threadIdx.x & 31, wid = threadIdx.x >> 5;
    if (lane == 0) ws[wid] = v;
    __syncthreads();
    if (wid == 0) {
        v = (lane < 8) ? ws[lane] : 0.0f;
        for (int o = 4; o > 0; o >>= 1) v += __shfl_down_sync(0xffffffffu, v, o);
    }
    return v;  // valid in thread 0
}

__global__ void k_zero() {
    int t = threadIdx.x;
    if (t < SUMN) { g_meanconf[t] = 0.0f; g_overlap[t] = 0.0f; }
    if (t < BATCH) g_demand[t] = 0.0f;
}

// Kernel 1: conf = sigmoid(max(ch0, ch1)) -> fp16; accumulate mean_conf[n], demand[b]
__global__ void __launch_bounds__(256) k_conf(const float* __restrict__ psm,
                                              const float* __restrict__ req) {
    int n    = blockIdx.x / BLOCKS_PER_IMG;
    int tile = blockIdx.x % BLOCKS_PER_IMG;
    int p0   = tile * 2048 + threadIdx.x * 8;

    const float* base0 = psm + (size_t)n * 2 * HW + p0;
    const float4 a4l = *(const float4*)(base0);
    const float4 a4h = *(const float4*)(base0 + 4);
    const float4 b4l = *(const float4*)(base0 + HW);
    const float4 b4h = *(const float4*)(base0 + HW + 4);
    float a[8] = {a4l.x, a4l.y, a4l.z, a4l.w, a4h.x, a4h.y, a4h.z, a4h.w};
    float b[8] = {b4l.x, b4l.y, b4l.z, b4l.w, b4h.x, b4h.y, b4h.z, b4h.w};

    __half hs[8];
    float sum = 0.0f;
    #pragma unroll
    for (int u = 0; u < 8; u++) {
        float m = fmaxf(a[u], b[u]);
        float s = __fdividef(1.0f, 1.0f + __expf(-m));
        hs[u] = __float2half_rn(s);
        sum += s;
    }
    *(uint4*)(g_conf + (size_t)n * HW + p0) = *(const uint4*)hs;

    float dsum = 0.0f;
    bool ego = ((n & (LAG - 1)) == 0);
    if (ego) {
        const float* rbase = req + (size_t)n * HW + p0;
        const float4 r4l = *(const float4*)(rbase);
        const float4 r4h = *(const float4*)(rbase + 4);
        dsum = r4l.x + r4l.y + r4l.z + r4l.w + r4h.x + r4h.y + r4h.z + r4h.w;
    }

    float bs = blockReduceSum256(sum);
    if (threadIdx.x == 0) atomicAdd(&g_meanconf[n], bs);
    __syncthreads();
    if (ego) {
        float bd = blockReduceSum256(dsum);
        if (threadIdx.x == 0) atomicAdd(&g_demand[n >> 3], bd);
    }
}

#define WBLOCKS_PER_IMG 144       // 147456 / (256*4)

// Kernel 2: warped = bilinear(conf[b,l], A=norm_affine[b,0,l]); overlap = sum Di*warped
__global__ void __launch_bounds__(256) k_warp(const float* __restrict__ req,
                                              const float* __restrict__ na) {
    int n    = blockIdx.x / WBLOCKS_PER_IMG;
    int tile = blockIdx.x % WBLOCKS_PER_IMG;
    int b = n >> 3, l = n & (LAG - 1);

    const float* A = na + (size_t)((b * LAG + 0) * LAG + l) * 6;
    float A00 = __ldg(A + 0), A01 = __ldg(A + 1), A02 = __ldg(A + 2);
    float A10 = __ldg(A + 3), A11 = __ldg(A + 4), A12 = __ldg(A + 5);

    const __half* cimg = g_conf + (size_t)n * HW;
    int p0 = tile * 1024 + threadIdx.x * 4;
    const float4 d4 = *(const float4*)(req + (size_t)(b * LAG) * HW + p0);
    float di[4] = {d4.x, d4.y, d4.z, d4.w};

    const float step = 2.0f / 383.0f;
    float sum = 0.0f;
    #pragma unroll
    for (int u = 0; u < 4; u++) {
        int p = p0 + u;
        int i = p / WDIM;
        int j = p - i * WDIM;
        float gx = fmaf((float)j, step, -1.0f);
        float gy = fmaf((float)i, step, -1.0f);
        float sx = fmaf(A00, gx, fmaf(A01, gy, A02));
        float sy = fmaf(A10, gx, fmaf(A11, gy, A12));
        float px = (sx + 1.0f) * (0.5f * (WDIM - 1));
        float py = (sy + 1.0f) * (0.5f * (HDIM - 1));
        float x0f = floorf(px), y0f = floorf(py);
        float wx = px - x0f, wy = py - y0f;
        int x0 = (int)x0f, y0 = (int)y0f;

        float v00 = 0.0f, v01 = 0.0f, v10 = 0.0f, v11 = 0.0f;
        bool xv0 = (unsigned)x0 < (unsigned)WDIM;
        bool xv1 = (unsigned)(x0 + 1) < (unsigned)WDIM;
        bool yv0 = (unsigned)y0 < (unsigned)HDIM;
        bool yv1 = (unsigned)(y0 + 1) < (unsigned)HDIM;
        if (yv0) {
            const __half* row = cimg + (size_t)y0 * WDIM;
            if (xv0) v00 = __half2float(__ldg(row + x0));
            if (xv1) v01 = __half2float(__ldg(row + x0 + 1));
        }
        if (yv1) {
            const __half* row = cimg + (size_t)(y0 + 1) * WDIM;
            if (xv0) v10 = __half2float(__ldg(row + x0));
            if (xv1) v11 = __half2float(__ldg(row + x0 + 1));
        }
        float top = v00 * (1.0f - wx) + v01 * wx;
        float bot = v10 * (1.0f - wx) + v11 * wx;
        float val = top * (1.0f - wy) + bot * wy;
        sum += di[u] * val;
    }

    float bs = blockReduceSum256(sum);
    if (threadIdx.x == 0) atomicAdd(&g_overlap[n], bs);
}

// Kernel 3: one block per output row r. 64 threads = one hidden unit each.
__global__ void __launch_bounds__(64)
k_head(const float* __restrict__ na,
       const float* __restrict__ qW1, const float* __restrict__ qb1,
       const float* __restrict__ qW2, const float* __restrict__ qb2,
       const float* __restrict__ kW1, const float* __restrict__ kb1,
       const float* __restrict__ kW2, const float* __restrict__ kb2,
       const float* __restrict__ eW1, const float* __restrict__ eb1,
       const float* __restrict__ eW2, const float* __restrict__ eb2,
       float* __restrict__ out) {
    int r = blockIdx.x;
    int b = r >> 3, l = r & (LAG - 1);
    int j = threadIdx.x;

    __shared__ float s_ego[8], s_feat[8];
    __shared__ float s_hq[64], s_hk[64], s_q[64], s_k[64];
    __shared__ float s_part[2];

    const float invHW = 1.0f / (float)HW;

    if (j == 0) {
        float dm  = g_demand[b] * invHW;
        float mc0 = g_meanconf[b * LAG] * invHW;
        s_ego[0] = mc0; s_ego[1] = dm; s_ego[2] = 0.0f; s_ego[3] = 0.0f;
        s_ego[4] = 1.0f; s_ego[5] = 0.0f; s_ego[6] = 0.0f; s_ego[7] = dm;

        float mc = g_meanconf[r] * invHW;
        float ov = g_overlap[r] * invHW;
        const float* A = na + (size_t)((b * LAG + 0) * LAG + l) * 6;
        float dx = A[2], dy = A[5];
        float dist = sqrtf(dx * dx + dy * dy);
        const float* D  = na + (size_t)((b * LAG + l) * LAG + l) * 6;
        const float* D0 = na + (size_t)((b * LAG + 0) * LAG + 0) * 6;
        float yaw  = atan2f(D[3], D[0]);
        float yaw0 = atan2f(D0[3], D0[0]);
        float d = yaw0 - yaw;
        s_feat[0] = mc; s_feat[1] = ov; s_feat[2] = dx; s_feat[3] = dy;
        s_feat[4] = cosf(d); s_feat[5] = sinf(d); s_feat[6] = dist; s_feat[7] = dm;
    }
    __syncthreads();

    // Layer 1 of q- and k-MLPs (8-wide input)
    {
        float aq = qb1[j], ak = kb1[j];
        #pragma unroll
        for (int i = 0; i < 8; i++) {
            aq = fmaf(s_ego[i],  qW1[i * 64 + j], aq);
            ak = fmaf(s_feat[i], kW1[i * 64 + j], ak);
        }
        s_hq[j] = fmaxf(aq, 0.0f);
        s_hk[j] = fmaxf(ak, 0.0f);
    }
    __syncthreads();

    // Layer 2 of q- and k-MLPs (64-wide)
    {
        float aq = qb2[j], ak = kb2[j];
        #pragma unroll
        for (int i = 0; i < 64; i++) {
            aq = fmaf(s_hq[i], qW2[i * 64 + j], aq);
            ak = fmaf(s_hk[i], kW2[i * 64 + j], ak);
        }
        s_q[j] = aq;
        s_k[j] = ak;
    }
    __syncthreads();

    // e-MLP hidden on [q, k] (128-wide), then dot with eW2
    float eh;
    {
        float acc = eb1[j];
        #pragma unroll
        for (int i = 0; i < 64; i++) acc = fmaf(s_q[i], eW1[i * 64 + j], acc);
        #pragma unroll
        for (int i = 0; i < 64; i++) acc = fmaf(s_k[i], eW1[(64 + i) * 64 + j], acc);
        eh = fmaxf(acc, 0.0f) * eW2[j];
    }
    // reduce 64 values (2 warps)
    for (int o = 16; o > 0; o >>= 1) eh += __shfl_down_sync(0xffffffffu, eh, o);
    if ((j & 31) == 0) s_part[j >> 5] = eh;
    __syncthreads();
    if (j == 0) {
        float logit = s_part[0] + s_part[1] + eb2[0];
        if (l == 0) logit = NEGV;
        float s = 1.0f / (1.0f + expf(-logit));
        out[r] = fminf(fmaxf(s, 0.0f), 1.0f);
    }
}

extern "C" void kernel_launch(void* const* d_in, const int* in_sizes, int n_in,
                              void* d_out, int out_size) {
    const float* psm  = (const float*)d_in[0];
    const float* req  = (const float*)d_in[1];
    const float* na   = (const float*)d_in[2];
    // d_in[3] = record_len (unused, always L)
    const float* qW1 = (const float*)d_in[4];
    const float* qb1 = (const float*)d_in[5];
    const float* qW2 = (const float*)d_in[6];
    const float* qb2 = (const float*)d_in[7];
    const float* kW1 = (const float*)d_in[8];
    const float* kb1 = (const float*)d_in[9];
    const float* kW2 = (const float*)d_in[10];
    const float* kb2 = (const float*)d_in[11];
    const float* eW1 = (const float*)d_in[12];
    const float* eb1 = (const float*)d_in[13];
    const float* eW2 = (const float*)d_in[14];
    const float* eb2 = (const float*)d_in[15];
    float* out = (float*)d_out;

    k_zero<<<1, 256>>>();
    k_conf<<<SUMN * BLOCKS_PER_IMG, 256>>>(psm, req);
    k_warp<<<SUMN * WBLOCKS_PER_IMG, 256>>>(req, na);
    k_head<<<SUMN, 64>>>(na, qW1, qb1, qW2, qb2, kW1, kb1, kW2, kb2,
                         eW1, eb1, eW2, eb2, out);
}